// round 4
// baseline (speedup 1.0000x reference)
#include <cuda_runtime.h>
#include <math.h>

// Problem constants
#define B_  2
#define S_  4096
#define D_  2048
#define H_  16
#define HD_ 128
#define MROWS (B_ * S_)   // 8192

// Scratch in __device__ globals (allocation-guard-safe)
__device__ float g_q [(size_t)MROWS * D_];
__device__ float g_k [(size_t)MROWS * D_];
__device__ float g_v [(size_t)MROWS * D_];
__device__ float g_ao[(size_t)MROWS * D_];

// ---------------------------------------------------------------------------
// SGEMM: C[m][n] = sum_k A[m][k] * Bw[n][k]   (both K-major, torch y = x @ W^T)
// 128x128 block tile, BK=16, 8x8 per thread, 256 threads.
// ---------------------------------------------------------------------------
__global__ void __launch_bounds__(256) sgemm_nt(const float* __restrict__ A,
                                                const float* __restrict__ Bw,
                                                float* __restrict__ C,
                                                int M, int N, int K)
{
    __shared__ float As[16][132];  // padded to 132 to break store conflicts
    __shared__ float Bs[16][132];

    const int tid = threadIdx.x;
    const int tx = tid & 15;        // 0..15  -> output cols tx*8..+8
    const int ty = tid >> 4;        // 0..15  -> output rows ty*8..+8
    const int bm = blockIdx.y * 128;
    const int bn = blockIdx.x * 128;

    const float* Ab = A  + (size_t)bm * K;
    const float* Bb = Bw + (size_t)bn * K;

    float acc[8][8];
#pragma unroll
    for (int i = 0; i < 8; i++)
#pragma unroll
        for (int j = 0; j < 8; j++) acc[i][j] = 0.0f;

    const int lr = tid >> 2;        // 0..63
    const int lc = (tid & 3) << 2;  // 0,4,8,12

    for (int k0 = 0; k0 < K; k0 += 16) {
        float4 a0 = *(const float4*)(Ab + (size_t)lr        * K + k0 + lc);
        float4 a1 = *(const float4*)(Ab + (size_t)(lr + 64) * K + k0 + lc);
        float4 b0 = *(const float4*)(Bb + (size_t)lr        * K + k0 + lc);
        float4 b1 = *(const float4*)(Bb + (size_t)(lr + 64) * K + k0 + lc);

        __syncthreads();
        As[lc+0][lr] = a0.x; As[lc+1][lr] = a0.y; As[lc+2][lr] = a0.z; As[lc+3][lr] = a0.w;
        As[lc+0][lr+64] = a1.x; As[lc+1][lr+64] = a1.y; As[lc+2][lr+64] = a1.z; As[lc+3][lr+64] = a1.w;
        Bs[lc+0][lr] = b0.x; Bs[lc+1][lr] = b0.y; Bs[lc+2][lr] = b0.z; Bs[lc+3][lr] = b0.w;
        Bs[lc+0][lr+64] = b1.x; Bs[lc+1][lr+64] = b1.y; Bs[lc+2][lr+64] = b1.z; Bs[lc+3][lr+64] = b1.w;
        __syncthreads();

#pragma unroll
        for (int kk = 0; kk < 16; kk++) {
            float ar[8], br[8];
            *(float4*)&ar[0] = *(const float4*)&As[kk][ty * 8];
            *(float4*)&ar[4] = *(const float4*)&As[kk][ty * 8 + 4];
            *(float4*)&br[0] = *(const float4*)&Bs[kk][tx * 8];
            *(float4*)&br[4] = *(const float4*)&Bs[kk][tx * 8 + 4];
#pragma unroll
            for (int i = 0; i < 8; i++)
#pragma unroll
                for (int j = 0; j < 8; j++)
                    acc[i][j] += ar[i] * br[j];
        }
    }

#pragma unroll
    for (int i = 0; i < 8; i++) {
        size_t row = (size_t)(bm + ty * 8 + i) * N + bn + tx * 8;
        *(float4*)&C[row]     = make_float4(acc[i][0], acc[i][1], acc[i][2], acc[i][3]);
        *(float4*)&C[row + 4] = make_float4(acc[i][4], acc[i][5], acc[i][6], acc[i][7]);
    }
}

// ---------------------------------------------------------------------------
// Per-head RMSNorm + RoPE, in place on q and k.
// One warp handles one (b,s,h) row of 128 elems (4 per lane).
// blockIdx.y: 0 -> q (norm_q_w), 1 -> k (norm_k_w)
// ---------------------------------------------------------------------------
__global__ void __launch_bounds__(256) rmsnorm_rope(float* __restrict__ qp,
                                                    float* __restrict__ kp,
                                                    const float* __restrict__ freqs,
                                                    const float* __restrict__ wq,
                                                    const float* __restrict__ wk)
{
    float* ptr      = blockIdx.y ? kp : qp;
    const float* w  = blockIdx.y ? wk : wq;

    const int warp = threadIdx.x >> 5;
    const int lane = threadIdx.x & 31;
    const size_t row = (size_t)blockIdx.x * 8 + warp;   // 0 .. B*S*H-1
    const size_t bs  = row >> 4;                        // (b*S + s)

    float4 xv = *(float4*)&ptr[row * HD_ + lane * 4];
    float ss = xv.x * xv.x + xv.y * xv.y + xv.z * xv.z + xv.w * xv.w;
#pragma unroll
    for (int off = 16; off; off >>= 1) ss += __shfl_xor_sync(0xffffffffu, ss, off);
    float r = rsqrtf(ss * (1.0f / 128.0f) + 1e-5f);

    float4 wv = *(const float4*)&w[lane * 4];
    float nr0 = xv.x * r * wv.x;
    float ni0 = xv.y * r * wv.y;
    float nr1 = xv.z * r * wv.z;
    float ni1 = xv.w * r * wv.w;

    const float* f = freqs + bs * HD_;
    float c0 = f[2 * lane],     c1 = f[2 * lane + 1];
    float s0 = f[64 + 2 * lane], s1 = f[64 + 2 * lane + 1];

    float4 o;
    o.x = nr0 * c0 - ni0 * s0;
    o.y = nr0 * s0 + ni0 * c0;
    o.z = nr1 * c1 - ni1 * s1;
    o.w = nr1 * s1 + ni1 * c1;
    *(float4*)&ptr[row * HD_ + lane * 4] = o;
}

// ---------------------------------------------------------------------------
// Flash attention, fp32, online softmax.
// Block = one (b, h, 64-row q tile), 256 threads (16x16).
// Thread (ty,tx): score micro-tile rows ty*4..+4, cols tx*4..+4;
//                 output micro-tile rows ty*4..+4, dims tx*8..+8.
// Shared: Qs[64][128], KsT[128][68] (transposed, padded to mult-of-4 for
// aligned LDS.128), Vs[64][128], Ps[64][68]
// ---------------------------------------------------------------------------
#define KST_PAD 68
#define FA_SMEM_FLOATS (64*128 + 128*KST_PAD + 64*128 + 64*68)

__global__ void __launch_bounds__(256, 1) flash_attn(const float* __restrict__ q,
                                                     const float* __restrict__ k,
                                                     const float* __restrict__ v,
                                                     float* __restrict__ out)
{
    extern __shared__ float sm[];
    float* Qs  = sm;                      // [64][128]
    float* KsT = Qs  + 64 * 128;          // [128][KST_PAD]
    float* Vs  = KsT + 128 * KST_PAD;     // [64][128]
    float* Ps  = Vs  + 64 * 128;          // [64][68]

    const int b  = blockIdx.z;
    const int h  = blockIdx.y;
    const int q0 = blockIdx.x * 64;
    const int tid = threadIdx.x;
    const int tx = tid & 15;
    const int ty = tid >> 4;

    const float scale = 0.08838834764831845f;  // 1/sqrt(128)

    // Load Q tile (rows q0..q0+63 of head h), coalesced float4
    for (int i = tid; i < 64 * 32; i += 256) {
        int r = i >> 5, c4 = i & 31;
        float4 val = *(const float4*)&q[(size_t)(b * S_ + q0 + r) * D_ + h * HD_ + c4 * 4];
        *(float4*)&Qs[r * 128 + c4 * 4] = val;
    }

    float m[4], l[4], acc[4][8];
#pragma unroll
    for (int i = 0; i < 4; i++) {
        m[i] = -INFINITY;
        l[i] = 0.0f;
#pragma unroll
        for (int d = 0; d < 8; d++) acc[i][d] = 0.0f;
    }

    for (int kv0 = 0; kv0 < S_; kv0 += 64) {
        __syncthreads();  // previous PV done (Vs/Ps free)

        // Load K (transposed into KsT) and V tiles
        for (int i = tid; i < 64 * 32; i += 256) {
            int r = i >> 5, c4 = i & 31;
            size_t gbase = (size_t)(b * S_ + kv0 + r) * D_ + h * HD_ + c4 * 4;
            float4 kv4 = *(const float4*)&k[gbase];
            KsT[(c4 * 4 + 0) * KST_PAD + r] = kv4.x;
            KsT[(c4 * 4 + 1) * KST_PAD + r] = kv4.y;
            KsT[(c4 * 4 + 2) * KST_PAD + r] = kv4.z;
            KsT[(c4 * 4 + 3) * KST_PAD + r] = kv4.w;
            float4 vv4 = *(const float4*)&v[gbase];
            *(float4*)&Vs[r * 128 + c4 * 4] = vv4;
        }
        __syncthreads();

        // Scores: s[i][j] = Q[ty*4+i] . K[tx*4+j]
        float s[4][4];
#pragma unroll
        for (int i = 0; i < 4; i++)
#pragma unroll
            for (int j = 0; j < 4; j++) s[i][j] = 0.0f;

#pragma unroll 4
        for (int d4 = 0; d4 < 32; d4++) {
            float4 q0v = *(const float4*)&Qs[(ty * 4 + 0) * 128 + d4 * 4];
            float4 q1v = *(const float4*)&Qs[(ty * 4 + 1) * 128 + d4 * 4];
            float4 q2v = *(const float4*)&Qs[(ty * 4 + 2) * 128 + d4 * 4];
            float4 q3v = *(const float4*)&Qs[(ty * 4 + 3) * 128 + d4 * 4];
            float qa[4][4] = {{q0v.x, q0v.y, q0v.z, q0v.w},
                              {q1v.x, q1v.y, q1v.z, q1v.w},
                              {q2v.x, q2v.y, q2v.z, q2v.w},
                              {q3v.x, q3v.y, q3v.z, q3v.w}};
#pragma unroll
            for (int dd = 0; dd < 4; dd++) {
                float4 kv4 = *(const float4*)&KsT[(d4 * 4 + dd) * KST_PAD + tx * 4];
#pragma unroll
                for (int i = 0; i < 4; i++) {
                    s[i][0] += qa[i][dd] * kv4.x;
                    s[i][1] += qa[i][dd] * kv4.y;
                    s[i][2] += qa[i][dd] * kv4.z;
                    s[i][3] += qa[i][dd] * kv4.w;
                }
            }
        }

        // Online softmax per row (16-lane groups share a row set)
        float alpha[4];
#pragma unroll
        for (int i = 0; i < 4; i++) {
#pragma unroll
            for (int j = 0; j < 4; j++) s[i][j] *= scale;
            float rm = fmaxf(fmaxf(s[i][0], s[i][1]), fmaxf(s[i][2], s[i][3]));
#pragma unroll
            for (int off = 8; off; off >>= 1)
                rm = fmaxf(rm, __shfl_xor_sync(0xffffffffu, rm, off));
            float mnew = fmaxf(m[i], rm);
            alpha[i] = __expf(m[i] - mnew);
            float rs = 0.0f;
#pragma unroll
            for (int j = 0; j < 4; j++) {
                s[i][j] = __expf(s[i][j] - mnew);
                rs += s[i][j];
            }
#pragma unroll
            for (int off = 8; off; off >>= 1)
                rs += __shfl_xor_sync(0xffffffffu, rs, off);
            l[i] = l[i] * alpha[i] + rs;
            m[i] = mnew;
            // rescale existing accumulator
#pragma unroll
            for (int d = 0; d < 8; d++) acc[i][d] *= alpha[i];
            // publish probabilities
            *(float4*)&Ps[(ty * 4 + i) * 68 + tx * 4] =
                make_float4(s[i][0], s[i][1], s[i][2], s[i][3]);
        }
        __syncthreads();

        // O += P @ V  (rows ty*4..+4, dims tx*8..+8)
#pragma unroll 4
        for (int j = 0; j < 64; j++) {
            float4 v0 = *(const float4*)&Vs[j * 128 + tx * 8];
            float4 v1 = *(const float4*)&Vs[j * 128 + tx * 8 + 4];
#pragma unroll
            for (int i = 0; i < 4; i++) {
                float p = Ps[(ty * 4 + i) * 68 + j];
                acc[i][0] += p * v0.x; acc[i][1] += p * v0.y;
                acc[i][2] += p * v0.z; acc[i][3] += p * v0.w;
                acc[i][4] += p * v1.x; acc[i][5] += p * v1.y;
                acc[i][6] += p * v1.z; acc[i][7] += p * v1.w;
            }
        }
    }

    // Normalize and write out: out[b, q0+row, h*128 + d]
#pragma unroll
    for (int i = 0; i < 4; i++) {
        float inv = 1.0f / l[i];
        size_t base = (size_t)(b * S_ + q0 + ty * 4 + i) * D_ + h * HD_ + tx * 8;
        *(float4*)&out[base]     = make_float4(acc[i][0] * inv, acc[i][1] * inv,
                                               acc[i][2] * inv, acc[i][3] * inv);
        *(float4*)&out[base + 4] = make_float4(acc[i][4] * inv, acc[i][5] * inv,
                                               acc[i][6] * inv, acc[i][7] * inv);
    }
}

// ---------------------------------------------------------------------------
// Launch
// ---------------------------------------------------------------------------
extern "C" void kernel_launch(void* const* d_in, const int* in_sizes, int n_in,
                              void* d_out, int out_size)
{
    const float* x     = (const float*)d_in[0];
    const float* freqs = (const float*)d_in[1];
    const float* wq    = (const float*)d_in[2];
    const float* wk    = (const float*)d_in[3];
    const float* wv    = (const float*)d_in[4];
    const float* wo    = (const float*)d_in[5];
    const float* nqw   = (const float*)d_in[6];
    const float* nkw   = (const float*)d_in[7];
    float* out = (float*)d_out;

    float *q, *k, *v, *ao;
    cudaGetSymbolAddress((void**)&q,  g_q);
    cudaGetSymbolAddress((void**)&k,  g_k);
    cudaGetSymbolAddress((void**)&v,  g_v);
    cudaGetSymbolAddress((void**)&ao, g_ao);

    dim3 gemm_grid(D_ / 128, MROWS / 128);  // (16, 64)

    sgemm_nt<<<gemm_grid, 256>>>(x, wq, q, MROWS, D_, D_);
    sgemm_nt<<<gemm_grid, 256>>>(x, wk, k, MROWS, D_, D_);
    sgemm_nt<<<gemm_grid, 256>>>(x, wv, v, MROWS, D_, D_);

    rmsnorm_rope<<<dim3(MROWS * H_ / 8, 2), 256>>>(q, k, freqs, nqw, nkw);

    int smem_bytes = FA_SMEM_FLOATS * sizeof(float);
    cudaFuncSetAttribute(flash_attn, cudaFuncAttributeMaxDynamicSharedMemorySize,
                         smem_bytes);
    flash_attn<<<dim3(S_ / 64, H_, B_), 256, smem_bytes>>>(q, k, v, ao);

    sgemm_nt<<<gemm_grid, 256>>>(ao, wo, out, MROWS, D_, D_);
}

// round 5
// speedup vs baseline: 1.3373x; 1.3373x over previous
#include <cuda_runtime.h>
#include <math.h>
#include <stdint.h>

// Problem constants
#define B_  2
#define S_  4096
#define D_  2048
#define H_  16
#define HD_ 128
#define MROWS (B_ * S_)   // 8192

// Scratch in __device__ globals (allocation-guard-safe)
__device__ float g_q [(size_t)MROWS * D_];
__device__ float g_k [(size_t)MROWS * D_];
__device__ float g_v [(size_t)MROWS * D_];
__device__ float g_ao[(size_t)MROWS * D_];

// ---------------------------------------------------------------------------
// tf32 helpers
// ---------------------------------------------------------------------------
__device__ __forceinline__ float tf32r(float x) {
    uint32_t u;
    asm("cvt.rna.tf32.f32 %0, %1;" : "=r"(u) : "f"(x));
    return __uint_as_float(u);
}

__device__ __forceinline__ void mma_tf32(float* c, const uint32_t* a, const uint32_t* b) {
    asm volatile(
        "mma.sync.aligned.m16n8k8.row.col.f32.tf32.tf32.f32 "
        "{%0,%1,%2,%3}, {%4,%5,%6,%7}, {%8,%9}, {%0,%1,%2,%3};\n"
        : "+f"(c[0]), "+f"(c[1]), "+f"(c[2]), "+f"(c[3])
        : "r"(a[0]), "r"(a[1]), "r"(a[2]), "r"(a[3]), "r"(b[0]), "r"(b[1]));
}

// ---------------------------------------------------------------------------
// tf32 tensor-core GEMM: C[m][n] = sum_k A[m][k] * Bw[n][k]
// 128x128 block tile, BK=32, 256 threads = 8 warps (2m x 4n), warp tile 64x32.
// mma.sync m16n8k8 tf32. Smem ld = 36 -> conflict-free fragment loads.
// ---------------------------------------------------------------------------
#define BK_ 32
#define LDT 36

__global__ void __launch_bounds__(256) tgemm_nt(const float* __restrict__ A,
                                                const float* __restrict__ Bw,
                                                float* __restrict__ C,
                                                int M, int N, int K)
{
    __shared__ float As[128][LDT];
    __shared__ float Bs[128][LDT];

    const int tid    = threadIdx.x;
    const int warp   = tid >> 5;
    const int lane   = tid & 31;
    const int warp_m = warp >> 2;      // 0..1 -> m offset *64
    const int warp_n = warp & 3;       // 0..3 -> n offset *32
    const int g      = lane >> 2;      // group 0..7
    const int tig    = lane & 3;       // thread-in-group 0..3

    const int bm = blockIdx.y * 128;
    const int bn = blockIdx.x * 128;

    const int lrow = tid >> 3;         // 0..31
    const int lk   = (tid & 7) * 4;    // 0,4,...,28

    float c[4][4][4];
#pragma unroll
    for (int mi = 0; mi < 4; mi++)
#pragma unroll
        for (int ni = 0; ni < 4; ni++)
#pragma unroll
            for (int j = 0; j < 4; j++) c[mi][ni][j] = 0.0f;

    for (int k0 = 0; k0 < K; k0 += BK_) {
        float4 av[4], bv[4];
#pragma unroll
        for (int r = 0; r < 4; r++) {
            av[r] = *(const float4*)(A  + (size_t)(bm + lrow + 32 * r) * K + k0 + lk);
            bv[r] = *(const float4*)(Bw + (size_t)(bn + lrow + 32 * r) * K + k0 + lk);
        }

        __syncthreads();   // previous compute phase done reading smem
#pragma unroll
        for (int r = 0; r < 4; r++) {
            As[lrow + 32 * r][lk + 0] = tf32r(av[r].x);
            As[lrow + 32 * r][lk + 1] = tf32r(av[r].y);
            As[lrow + 32 * r][lk + 2] = tf32r(av[r].z);
            As[lrow + 32 * r][lk + 3] = tf32r(av[r].w);
            Bs[lrow + 32 * r][lk + 0] = tf32r(bv[r].x);
            Bs[lrow + 32 * r][lk + 1] = tf32r(bv[r].y);
            Bs[lrow + 32 * r][lk + 2] = tf32r(bv[r].z);
            Bs[lrow + 32 * r][lk + 3] = tf32r(bv[r].w);
        }
        __syncthreads();

#pragma unroll
        for (int kk = 0; kk < BK_ / 8; kk++) {
            uint32_t a[4][4], b[4][2];
#pragma unroll
            for (int mi = 0; mi < 4; mi++) {
                int row = warp_m * 64 + mi * 16;
                a[mi][0] = __float_as_uint(As[row + g    ][kk * 8 + tig]);
                a[mi][1] = __float_as_uint(As[row + 8 + g][kk * 8 + tig]);
                a[mi][2] = __float_as_uint(As[row + g    ][kk * 8 + tig + 4]);
                a[mi][3] = __float_as_uint(As[row + 8 + g][kk * 8 + tig + 4]);
            }
#pragma unroll
            for (int ni = 0; ni < 4; ni++) {
                int col = warp_n * 32 + ni * 8;
                b[ni][0] = __float_as_uint(Bs[col + g][kk * 8 + tig]);
                b[ni][1] = __float_as_uint(Bs[col + g][kk * 8 + tig + 4]);
            }
#pragma unroll
            for (int mi = 0; mi < 4; mi++)
#pragma unroll
                for (int ni = 0; ni < 4; ni++)
                    mma_tf32(c[mi][ni], a[mi], b[ni]);
        }
    }

    // Writeback: c0,c1 -> (row g, cols 2tig,2tig+1); c2,c3 -> row g+8
#pragma unroll
    for (int mi = 0; mi < 4; mi++) {
#pragma unroll
        for (int ni = 0; ni < 4; ni++) {
            int row0 = bm + warp_m * 64 + mi * 16 + g;
            int col  = bn + warp_n * 32 + ni * 8 + 2 * tig;
            *(float2*)&C[(size_t)row0 * N + col] =
                make_float2(c[mi][ni][0], c[mi][ni][1]);
            *(float2*)&C[(size_t)(row0 + 8) * N + col] =
                make_float2(c[mi][ni][2], c[mi][ni][3]);
        }
    }
}

// ---------------------------------------------------------------------------
// Per-head RMSNorm + RoPE, in place on q and k.
// ---------------------------------------------------------------------------
__global__ void __launch_bounds__(256) rmsnorm_rope(float* __restrict__ qp,
                                                    float* __restrict__ kp,
                                                    const float* __restrict__ freqs,
                                                    const float* __restrict__ wq,
                                                    const float* __restrict__ wk)
{
    float* ptr      = blockIdx.y ? kp : qp;
    const float* w  = blockIdx.y ? wk : wq;

    const int warp = threadIdx.x >> 5;
    const int lane = threadIdx.x & 31;
    const size_t row = (size_t)blockIdx.x * 8 + warp;   // 0 .. B*S*H-1
    const size_t bs  = row >> 4;                        // (b*S + s)

    float4 xv = *(float4*)&ptr[row * HD_ + lane * 4];
    float ss = xv.x * xv.x + xv.y * xv.y + xv.z * xv.z + xv.w * xv.w;
#pragma unroll
    for (int off = 16; off; off >>= 1) ss += __shfl_xor_sync(0xffffffffu, ss, off);
    float r = rsqrtf(ss * (1.0f / 128.0f) + 1e-5f);

    float4 wv = *(const float4*)&w[lane * 4];
    float nr0 = xv.x * r * wv.x;
    float ni0 = xv.y * r * wv.y;
    float nr1 = xv.z * r * wv.z;
    float ni1 = xv.w * r * wv.w;

    const float* f = freqs + bs * HD_;
    float c0 = f[2 * lane],     c1 = f[2 * lane + 1];
    float s0 = f[64 + 2 * lane], s1 = f[64 + 2 * lane + 1];

    float4 o;
    o.x = nr0 * c0 - ni0 * s0;
    o.y = nr0 * s0 + ni0 * c0;
    o.z = nr1 * c1 - ni1 * s1;
    o.w = nr1 * s1 + ni1 * c1;
    *(float4*)&ptr[row * HD_ + lane * 4] = o;
}

// ---------------------------------------------------------------------------
// Flash attention, fp32, online softmax (unchanged from passing baseline).
// ---------------------------------------------------------------------------
#define KST_PAD 68
#define FA_SMEM_FLOATS (64*128 + 128*KST_PAD + 64*128 + 64*68)

__global__ void __launch_bounds__(256, 1) flash_attn(const float* __restrict__ q,
                                                     const float* __restrict__ k,
                                                     const float* __restrict__ v,
                                                     float* __restrict__ out)
{
    extern __shared__ float sm[];
    float* Qs  = sm;                      // [64][128]
    float* KsT = Qs  + 64 * 128;          // [128][KST_PAD]
    float* Vs  = KsT + 128 * KST_PAD;     // [64][128]
    float* Ps  = Vs  + 64 * 128;          // [64][68]

    const int b  = blockIdx.z;
    const int h  = blockIdx.y;
    const int q0 = blockIdx.x * 64;
    const int tid = threadIdx.x;
    const int tx = tid & 15;
    const int ty = tid >> 4;

    const float scale = 0.08838834764831845f;  // 1/sqrt(128)

    for (int i = tid; i < 64 * 32; i += 256) {
        int r = i >> 5, c4 = i & 31;
        float4 val = *(const float4*)&q[(size_t)(b * S_ + q0 + r) * D_ + h * HD_ + c4 * 4];
        *(float4*)&Qs[r * 128 + c4 * 4] = val;
    }

    float m[4], l[4], acc[4][8];
#pragma unroll
    for (int i = 0; i < 4; i++) {
        m[i] = -INFINITY;
        l[i] = 0.0f;
#pragma unroll
        for (int d = 0; d < 8; d++) acc[i][d] = 0.0f;
    }

    for (int kv0 = 0; kv0 < S_; kv0 += 64) {
        __syncthreads();  // previous PV done (Vs/Ps free)

        for (int i = tid; i < 64 * 32; i += 256) {
            int r = i >> 5, c4 = i & 31;
            size_t gbase = (size_t)(b * S_ + kv0 + r) * D_ + h * HD_ + c4 * 4;
            float4 kv4 = *(const float4*)&k[gbase];
            KsT[(c4 * 4 + 0) * KST_PAD + r] = kv4.x;
            KsT[(c4 * 4 + 1) * KST_PAD + r] = kv4.y;
            KsT[(c4 * 4 + 2) * KST_PAD + r] = kv4.z;
            KsT[(c4 * 4 + 3) * KST_PAD + r] = kv4.w;
            float4 vv4 = *(const float4*)&v[gbase];
            *(float4*)&Vs[r * 128 + c4 * 4] = vv4;
        }
        __syncthreads();

        float s[4][4];
#pragma unroll
        for (int i = 0; i < 4; i++)
#pragma unroll
            for (int j = 0; j < 4; j++) s[i][j] = 0.0f;

#pragma unroll 4
        for (int d4 = 0; d4 < 32; d4++) {
            float4 q0v = *(const float4*)&Qs[(ty * 4 + 0) * 128 + d4 * 4];
            float4 q1v = *(const float4*)&Qs[(ty * 4 + 1) * 128 + d4 * 4];
            float4 q2v = *(const float4*)&Qs[(ty * 4 + 2) * 128 + d4 * 4];
            float4 q3v = *(const float4*)&Qs[(ty * 4 + 3) * 128 + d4 * 4];
            float qa[4][4] = {{q0v.x, q0v.y, q0v.z, q0v.w},
                              {q1v.x, q1v.y, q1v.z, q1v.w},
                              {q2v.x, q2v.y, q2v.z, q2v.w},
                              {q3v.x, q3v.y, q3v.z, q3v.w}};
#pragma unroll
            for (int dd = 0; dd < 4; dd++) {
                float4 kv4 = *(const float4*)&KsT[(d4 * 4 + dd) * KST_PAD + tx * 4];
#pragma unroll
                for (int i = 0; i < 4; i++) {
                    s[i][0] += qa[i][dd] * kv4.x;
                    s[i][1] += qa[i][dd] * kv4.y;
                    s[i][2] += qa[i][dd] * kv4.z;
                    s[i][3] += qa[i][dd] * kv4.w;
                }
            }
        }

        float alpha[4];
#pragma unroll
        for (int i = 0; i < 4; i++) {
#pragma unroll
            for (int j = 0; j < 4; j++) s[i][j] *= scale;
            float rm = fmaxf(fmaxf(s[i][0], s[i][1]), fmaxf(s[i][2], s[i][3]));
#pragma unroll
            for (int off = 8; off; off >>= 1)
                rm = fmaxf(rm, __shfl_xor_sync(0xffffffffu, rm, off));
            float mnew = fmaxf(m[i], rm);
            alpha[i] = __expf(m[i] - mnew);
            float rs = 0.0f;
#pragma unroll
            for (int j = 0; j < 4; j++) {
                s[i][j] = __expf(s[i][j] - mnew);
                rs += s[i][j];
            }
#pragma unroll
            for (int off = 8; off; off >>= 1)
                rs += __shfl_xor_sync(0xffffffffu, rs, off);
            l[i] = l[i] * alpha[i] + rs;
            m[i] = mnew;
#pragma unroll
            for (int d = 0; d < 8; d++) acc[i][d] *= alpha[i];
            *(float4*)&Ps[(ty * 4 + i) * 68 + tx * 4] =
                make_float4(s[i][0], s[i][1], s[i][2], s[i][3]);
        }
        __syncthreads();

#pragma unroll 4
        for (int j = 0; j < 64; j++) {
            float4 v0 = *(const float4*)&Vs[j * 128 + tx * 8];
            float4 v1 = *(const float4*)&Vs[j * 128 + tx * 8 + 4];
#pragma unroll
            for (int i = 0; i < 4; i++) {
                float p = Ps[(ty * 4 + i) * 68 + j];
                acc[i][0] += p * v0.x; acc[i][1] += p * v0.y;
                acc[i][2] += p * v0.z; acc[i][3] += p * v0.w;
                acc[i][4] += p * v1.x; acc[i][5] += p * v1.y;
                acc[i][6] += p * v1.z; acc[i][7] += p * v1.w;
            }
        }
    }

#pragma unroll
    for (int i = 0; i < 4; i++) {
        float inv = 1.0f / l[i];
        size_t base = (size_t)(b * S_ + q0 + ty * 4 + i) * D_ + h * HD_ + tx * 8;
        *(float4*)&out[base]     = make_float4(acc[i][0] * inv, acc[i][1] * inv,
                                               acc[i][2] * inv, acc[i][3] * inv);
        *(float4*)&out[base + 4] = make_float4(acc[i][4] * inv, acc[i][5] * inv,
                                               acc[i][6] * inv, acc[i][7] * inv);
    }
}

// ---------------------------------------------------------------------------
// Launch
// ---------------------------------------------------------------------------
extern "C" void kernel_launch(void* const* d_in, const int* in_sizes, int n_in,
                              void* d_out, int out_size)
{
    const float* x     = (const float*)d_in[0];
    const float* freqs = (const float*)d_in[1];
    const float* wq    = (const float*)d_in[2];
    const float* wk    = (const float*)d_in[3];
    const float* wv    = (const float*)d_in[4];
    const float* wo    = (const float*)d_in[5];
    const float* nqw   = (const float*)d_in[6];
    const float* nkw   = (const float*)d_in[7];
    float* out = (float*)d_out;

    float *q, *k, *v, *ao;
    cudaGetSymbolAddress((void**)&q,  g_q);
    cudaGetSymbolAddress((void**)&k,  g_k);
    cudaGetSymbolAddress((void**)&v,  g_v);
    cudaGetSymbolAddress((void**)&ao, g_ao);

    dim3 gemm_grid(D_ / 128, MROWS / 128);  // (16, 64)

    tgemm_nt<<<gemm_grid, 256>>>(x, wq, q, MROWS, D_, D_);
    tgemm_nt<<<gemm_grid, 256>>>(x, wk, k, MROWS, D_, D_);
    tgemm_nt<<<gemm_grid, 256>>>(x, wv, v, MROWS, D_, D_);

    rmsnorm_rope<<<dim3(MROWS * H_ / 8, 2), 256>>>(q, k, freqs, nqw, nkw);

    int smem_bytes = FA_SMEM_FLOATS * sizeof(float);
    cudaFuncSetAttribute(flash_attn, cudaFuncAttributeMaxDynamicSharedMemorySize,
                         smem_bytes);
    flash_attn<<<dim3(S_ / 64, H_, B_), 256, smem_bytes>>>(q, k, v, ao);

    tgemm_nt<<<gemm_grid, 256>>>(ao, wo, out, MROWS, D_, D_);
}

// round 7
// speedup vs baseline: 1.7092x; 1.2781x over previous
#include <cuda_runtime.h>
#include <math.h>
#include <stdint.h>

// Problem constants
#define B_  2
#define S_  4096
#define D_  2048
#define H_  16
#define HD_ 128
#define MROWS (B_ * S_)   // 8192

// Scratch in __device__ globals (allocation-guard-safe)
__device__ float g_q [(size_t)MROWS * D_];
__device__ float g_k [(size_t)MROWS * D_];
__device__ float g_v [(size_t)MROWS * D_];
__device__ float g_ao[(size_t)MROWS * D_];

// ---------------------------------------------------------------------------
// tf32 helpers
// ---------------------------------------------------------------------------
__device__ __forceinline__ float tf32r(float x) {
    uint32_t u;
    asm("cvt.rna.tf32.f32 %0, %1;" : "=r"(u) : "f"(x));
    return __uint_as_float(u);
}

__device__ __forceinline__ void mma_tf32(float* c, const uint32_t* a, const uint32_t* b) {
    asm volatile(
        "mma.sync.aligned.m16n8k8.row.col.f32.tf32.tf32.f32 "
        "{%0,%1,%2,%3}, {%4,%5,%6,%7}, {%8,%9}, {%0,%1,%2,%3};\n"
        : "+f"(c[0]), "+f"(c[1]), "+f"(c[2]), "+f"(c[3])
        : "r"(a[0]), "r"(a[1]), "r"(a[2]), "r"(a[3]), "r"(b[0]), "r"(b[1]));
}

// ---------------------------------------------------------------------------
// 3-pass split-tf32 GEMM (near-fp32 accuracy):
//   C[m][n] = sum_k A[m][k] * Bw[n][k]
// 128x128 tile, BK=32, 256 threads = 8 warps (2m x 4n), warp tile 64x32.
// Double-buffered smem stages; hi/lo split stored separately.
//   C = Ahi*Bhi + Ahi*Blo + Alo*Bhi
// ---------------------------------------------------------------------------
#define LDT 36
#define GSTAGE (128 * LDT)           // floats per (array, stage)
#define GEMM_SMEM_FLOATS (8 * GSTAGE)  // Ah,Al,Bh,Bl x 2 stages

__global__ void __launch_bounds__(256, 1) tgemm3_nt(const float* __restrict__ A,
                                                    const float* __restrict__ Bw,
                                                    float* __restrict__ C,
                                                    int M, int N, int K)
{
    extern __shared__ float sg[];
    float* Ah = sg;                  // [2][128][LDT]
    float* Al = Ah + 2 * GSTAGE;
    float* Bh = Al + 2 * GSTAGE;
    float* Bl = Bh + 2 * GSTAGE;

    const int tid    = threadIdx.x;
    const int warp   = tid >> 5;
    const int lane   = tid & 31;
    const int warp_m = warp >> 2;      // 0..1 -> m offset *64
    const int warp_n = warp & 3;       // 0..3 -> n offset *32
    const int g      = lane >> 2;      // group 0..7
    const int tig    = lane & 3;       // thread-in-group 0..3

    const int bm = blockIdx.y * 128;
    const int bn = blockIdx.x * 128;

    const int lrow = tid >> 3;         // 0..31
    const int lk   = (tid & 7) * 4;    // 0,4,...,28

    float c[4][4][4];
#pragma unroll
    for (int mi = 0; mi < 4; mi++)
#pragma unroll
        for (int ni = 0; ni < 4; ni++)
#pragma unroll
            for (int j = 0; j < 4; j++) c[mi][ni][j] = 0.0f;

    float4 av[4], bv[4];
    // prologue load k0 = 0
#pragma unroll
    for (int r = 0; r < 4; r++) {
        av[r] = *(const float4*)(A  + (size_t)(bm + lrow + 32 * r) * K + lk);
        bv[r] = *(const float4*)(Bw + (size_t)(bn + lrow + 32 * r) * K + lk);
    }

    const int iters = K / 32;
    for (int it = 0; it < iters; it++) {
        const int st = (it & 1) * GSTAGE;

        // split + store current regs into stage st
#pragma unroll
        for (int r = 0; r < 4; r++) {
            float4 hi, lo;
            hi.x = tf32r(av[r].x); lo.x = tf32r(av[r].x - hi.x);
            hi.y = tf32r(av[r].y); lo.y = tf32r(av[r].y - hi.y);
            hi.z = tf32r(av[r].z); lo.z = tf32r(av[r].z - hi.z);
            hi.w = tf32r(av[r].w); lo.w = tf32r(av[r].w - hi.w);
            *(float4*)&Ah[st + (lrow + 32 * r) * LDT + lk] = hi;
            *(float4*)&Al[st + (lrow + 32 * r) * LDT + lk] = lo;
            hi.x = tf32r(bv[r].x); lo.x = tf32r(bv[r].x - hi.x);
            hi.y = tf32r(bv[r].y); lo.y = tf32r(bv[r].y - hi.y);
            hi.z = tf32r(bv[r].z); lo.z = tf32r(bv[r].z - hi.z);
            hi.w = tf32r(bv[r].w); lo.w = tf32r(bv[r].w - hi.w);
            *(float4*)&Bh[st + (lrow + 32 * r) * LDT + lk] = hi;
            *(float4*)&Bl[st + (lrow + 32 * r) * LDT + lk] = lo;
        }
        __syncthreads();

        // prefetch next chunk
        if (it + 1 < iters) {
            const int k0 = (it + 1) * 32;
#pragma unroll
            for (int r = 0; r < 4; r++) {
                av[r] = *(const float4*)(A  + (size_t)(bm + lrow + 32 * r) * K + k0 + lk);
                bv[r] = *(const float4*)(Bw + (size_t)(bn + lrow + 32 * r) * K + k0 + lk);
            }
        }

        // compute on stage st
#pragma unroll
        for (int kk = 0; kk < 4; kk++) {
            uint32_t ahi[4][4], alo[4][4], bhi[4][2], blo[4][2];
#pragma unroll
            for (int mi = 0; mi < 4; mi++) {
                int row = warp_m * 64 + mi * 16;
                int base0 = st + (row + g)     * LDT + kk * 8 + tig;
                int base1 = st + (row + 8 + g) * LDT + kk * 8 + tig;
                ahi[mi][0] = __float_as_uint(Ah[base0]);
                ahi[mi][1] = __float_as_uint(Ah[base1]);
                ahi[mi][2] = __float_as_uint(Ah[base0 + 4]);
                ahi[mi][3] = __float_as_uint(Ah[base1 + 4]);
                alo[mi][0] = __float_as_uint(Al[base0]);
                alo[mi][1] = __float_as_uint(Al[base1]);
                alo[mi][2] = __float_as_uint(Al[base0 + 4]);
                alo[mi][3] = __float_as_uint(Al[base1 + 4]);
            }
#pragma unroll
            for (int ni = 0; ni < 4; ni++) {
                int col = warp_n * 32 + ni * 8;
                int base = st + (col + g) * LDT + kk * 8 + tig;
                bhi[ni][0] = __float_as_uint(Bh[base]);
                bhi[ni][1] = __float_as_uint(Bh[base + 4]);
                blo[ni][0] = __float_as_uint(Bl[base]);
                blo[ni][1] = __float_as_uint(Bl[base + 4]);
            }
#pragma unroll
            for (int mi = 0; mi < 4; mi++)
#pragma unroll
                for (int ni = 0; ni < 4; ni++) {
                    mma_tf32(c[mi][ni], ahi[mi], bhi[ni]);
                    mma_tf32(c[mi][ni], ahi[mi], blo[ni]);
                    mma_tf32(c[mi][ni], alo[mi], bhi[ni]);
                }
        }
        __syncthreads();
    }

#pragma unroll
    for (int mi = 0; mi < 4; mi++) {
#pragma unroll
        for (int ni = 0; ni < 4; ni++) {
            int row0 = bm + warp_m * 64 + mi * 16 + g;
            int col  = bn + warp_n * 32 + ni * 8 + 2 * tig;
            *(float2*)&C[(size_t)row0 * N + col] =
                make_float2(c[mi][ni][0], c[mi][ni][1]);
            *(float2*)&C[(size_t)(row0 + 8) * N + col] =
                make_float2(c[mi][ni][2], c[mi][ni][3]);
        }
    }
}

// ---------------------------------------------------------------------------
// Per-head RMSNorm + RoPE, in place on q and k.
// ---------------------------------------------------------------------------
__global__ void __launch_bounds__(256) rmsnorm_rope(float* __restrict__ qp,
                                                    float* __restrict__ kp,
                                                    const float* __restrict__ freqs,
                                                    const float* __restrict__ wq,
                                                    const float* __restrict__ wk)
{
    float* ptr      = blockIdx.y ? kp : qp;
    const float* w  = blockIdx.y ? wk : wq;

    const int warp = threadIdx.x >> 5;
    const int lane = threadIdx.x & 31;
    const size_t row = (size_t)blockIdx.x * 8 + warp;   // 0 .. B*S*H-1
    const size_t bs  = row >> 4;                        // (b*S + s)

    float4 xv = *(float4*)&ptr[row * HD_ + lane * 4];
    float ss = xv.x * xv.x + xv.y * xv.y + xv.z * xv.z + xv.w * xv.w;
#pragma unroll
    for (int off = 16; off; off >>= 1) ss += __shfl_xor_sync(0xffffffffu, ss, off);
    float r = rsqrtf(ss * (1.0f / 128.0f) + 1e-5f);

    float4 wv = *(const float4*)&w[lane * 4];
    float nr0 = xv.x * r * wv.x;
    float ni0 = xv.y * r * wv.y;
    float nr1 = xv.z * r * wv.z;
    float ni1 = xv.w * r * wv.w;

    const float* f = freqs + bs * HD_;
    float c0 = f[2 * lane],     c1 = f[2 * lane + 1];
    float s0 = f[64 + 2 * lane], s1 = f[64 + 2 * lane + 1];

    float4 o;
    o.x = nr0 * c0 - ni0 * s0;
    o.y = nr0 * s0 + ni0 * c0;
    o.z = nr1 * c1 - ni1 * s1;
    o.w = nr1 * s1 + ni1 * c1;
    *(float4*)&ptr[row * HD_ + lane * 4] = o;
}

// ---------------------------------------------------------------------------
// Tensor-core flash attention (tf32 mma, fp32 softmax/accum).
// Br=128 q rows per CTA, Bc=64 kv per tile, 8 warps x 16 rows.
// All smem operands in FRAGMENT-MAJOR layout (conflict-free wide LDS):
//   Qf[w][kk=16][lane][4]  a-frags of Q (pre-scaled by 1/sqrt(hd))
//   Kf[kk=16][nt=8][lane][2]  b-frags of K
//   Vf[kk=8][nt=16][lane][2]  b-frags of V
//   Pf[w][kk=8][lane][4]   a-frags of P (per-warp private)
// ---------------------------------------------------------------------------
#define FQF (8 * 16 * 128)   // 16384 floats
#define FKF (16 * 8 * 64)    // 8192
#define FVF (8 * 16 * 64)    // 8192
#define FPF (8 * 8 * 128)    // 8192
#define FA_SMEM_FLOATS (FQF + FKF + FVF + FPF)   // 40960 floats = 160KB

__global__ void __launch_bounds__(256, 1) flash_attn_tc(const float* __restrict__ q,
                                                        const float* __restrict__ k,
                                                        const float* __restrict__ v,
                                                        float* __restrict__ out)
{
    extern __shared__ float sm[];
    float* Qf = sm;
    float* Kf = Qf + FQF;
    float* Vf = Kf + FKF;
    float* Pf = Vf + FVF;

    const int b   = blockIdx.z;
    const int h   = blockIdx.y;
    const int q0  = blockIdx.x * 128;
    const int tid = threadIdx.x;
    const int w   = tid >> 5;
    const int lane = tid & 31;
    const int g   = lane >> 2;
    const int tig = lane & 3;

    const float scale = 0.08838834764831845f;  // 1/sqrt(128)

    // ---- Load Q tile into fragment-major smem, pre-scaled, tf32-rounded ----
    for (int i = tid; i < 128 * 32; i += 256) {
        int r  = i >> 5;
        int c0 = (i & 31) * 4;
        float4 val = *(const float4*)&q[(size_t)(b * S_ + q0 + r) * D_ + h * HD_ + c0];
        int wd = r >> 4, gg = r & 15;
        int rowhi = gg >> 3, gd = gg & 7;
        int kk = c0 >> 3, hi = (c0 >> 2) & 1;
        int jb = hi * 2 + rowhi;
        float vals[4] = {val.x, val.y, val.z, val.w};
#pragma unroll
        for (int j4 = 0; j4 < 4; j4++) {
            int laned = 4 * gd + j4;
            Qf[((wd * 16 + kk) * 32 + laned) * 4 + jb] = tf32r(vals[j4] * scale);
        }
    }

    float m[2], l[2], o[16][4];
    m[0] = m[1] = -INFINITY;
    l[0] = l[1] = 0.0f;
#pragma unroll
    for (int nt = 0; nt < 16; nt++)
#pragma unroll
        for (int j = 0; j < 4; j++) o[nt][j] = 0.0f;

    for (int kv0 = 0; kv0 < S_; kv0 += 64) {
        __syncthreads();   // Kf/Vf free (prev tile done); also covers Qf on iter 0

        // ---- Load K,V tiles into fragment-major smem ----
        for (int i = tid; i < 64 * 32; i += 256) {
            int r  = i >> 5;
            int c0 = (i & 31) * 4;
            size_t gbase = (size_t)(b * S_ + kv0 + r) * D_ + h * HD_ + c0;
            // K: n = kv row (r), k = dim (c)
            {
                float4 val = *(const float4*)&k[gbase];
                int nt = r >> 3, gd = r & 7;
                int kk = c0 >> 3, slot = (c0 >> 2) & 1;
                float vals[4] = {val.x, val.y, val.z, val.w};
#pragma unroll
                for (int j4 = 0; j4 < 4; j4++) {
                    int laned = 4 * gd + j4;
                    Kf[((kk * 8 + nt) * 32 + laned) * 2 + slot] = tf32r(vals[j4]);
                }
            }
            // V: k = kv row (r), n = dim (c)
            {
                float4 val = *(const float4*)&v[gbase];
                int kk = r >> 3, tv = r & 7;
                int slot = tv >> 2, tg = tv & 3;
                int nt = c0 >> 3;
                int g0 = c0 & 7;
                float vals[4] = {val.x, val.y, val.z, val.w};
#pragma unroll
                for (int j4 = 0; j4 < 4; j4++) {
                    int laned = 4 * (g0 + j4) + tg;
                    Vf[((kk * 16 + nt) * 32 + laned) * 2 + slot] = tf32r(vals[j4]);
                }
            }
        }
        __syncthreads();

        // ---- S = Q K^T (scaled already) ----
        float sc[8][4];
#pragma unroll
        for (int nt = 0; nt < 8; nt++)
#pragma unroll
            for (int j = 0; j < 4; j++) sc[nt][j] = 0.0f;

#pragma unroll
        for (int kk = 0; kk < 16; kk++) {
            float4 a4 = *(const float4*)&Qf[((w * 16 + kk) * 32 + lane) * 4];
            uint32_t a[4] = {__float_as_uint(a4.x), __float_as_uint(a4.y),
                             __float_as_uint(a4.z), __float_as_uint(a4.w)};
#pragma unroll
            for (int nt = 0; nt < 8; nt++) {
                float2 b2 = *(const float2*)&Kf[((kk * 8 + nt) * 32 + lane) * 2];
                uint32_t bb[2] = {__float_as_uint(b2.x), __float_as_uint(b2.y)};
                mma_tf32(sc[nt], a, bb);
            }
        }

        // ---- online softmax (rows g and g+8 of this warp's 16-row block) ----
#pragma unroll
        for (int rh = 0; rh < 2; rh++) {
            int i0 = rh * 2;
            float rm = -INFINITY;
#pragma unroll
            for (int nt = 0; nt < 8; nt++)
                rm = fmaxf(rm, fmaxf(sc[nt][i0], sc[nt][i0 + 1]));
            rm = fmaxf(rm, __shfl_xor_sync(0xffffffffu, rm, 1));
            rm = fmaxf(rm, __shfl_xor_sync(0xffffffffu, rm, 2));
            float mnew = fmaxf(m[rh], rm);
            float alpha = __expf(m[rh] - mnew);
            float rs = 0.0f;
#pragma unroll
            for (int nt = 0; nt < 8; nt++) {
                sc[nt][i0]     = __expf(sc[nt][i0]     - mnew);
                sc[nt][i0 + 1] = __expf(sc[nt][i0 + 1] - mnew);
                rs += sc[nt][i0] + sc[nt][i0 + 1];
            }
            rs += __shfl_xor_sync(0xffffffffu, rs, 1);
            rs += __shfl_xor_sync(0xffffffffu, rs, 2);
            l[rh] = l[rh] * alpha + rs;
            m[rh] = mnew;
#pragma unroll
            for (int nt = 0; nt < 16; nt++) {
                o[nt][i0]     *= alpha;
                o[nt][i0 + 1] *= alpha;
            }
        }

        // ---- store P fragments (per-warp private region) ----
#pragma unroll
        for (int nt = 0; nt < 8; nt++) {
#pragma unroll
            for (int e = 0; e < 2; e++) {
                int t  = 2 * tig + e;
                int hi = t >> 2, tg = t & 3;
                int laned = 4 * g + tg;
#pragma unroll
                for (int rh = 0; rh < 2; rh++) {
                    int jb = hi * 2 + rh;
                    Pf[((w * 8 + nt) * 32 + laned) * 4 + jb] = tf32r(sc[nt][rh * 2 + e]);
                }
            }
        }
        __syncwarp();

        // ---- O += P V ----
#pragma unroll
        for (int kk = 0; kk < 8; kk++) {
            float4 a4 = *(const float4*)&Pf[((w * 8 + kk) * 32 + lane) * 4];
            uint32_t a[4] = {__float_as_uint(a4.x), __float_as_uint(a4.y),
                             __float_as_uint(a4.z), __float_as_uint(a4.w)};
#pragma unroll
            for (int nt = 0; nt < 16; nt++) {
                float2 b2 = *(const float2*)&Vf[((kk * 16 + nt) * 32 + lane) * 2];
                uint32_t bb[2] = {__float_as_uint(b2.x), __float_as_uint(b2.y)};
                mma_tf32(o[nt], a, bb);
            }
        }
    }

    // ---- normalize + write out ----
    float inv0 = 1.0f / l[0];
    float inv1 = 1.0f / l[1];
    size_t row0 = (size_t)(b * S_ + q0 + w * 16 + g);
    size_t row1 = row0 + 8;
#pragma unroll
    for (int nt = 0; nt < 16; nt++) {
        int col = h * HD_ + nt * 8 + 2 * tig;
        *(float2*)&out[row0 * D_ + col] = make_float2(o[nt][0] * inv0, o[nt][1] * inv0);
        *(float2*)&out[row1 * D_ + col] = make_float2(o[nt][2] * inv1, o[nt][3] * inv1);
    }
}

// ---------------------------------------------------------------------------
// Launch
// ---------------------------------------------------------------------------
extern "C" void kernel_launch(void* const* d_in, const int* in_sizes, int n_in,
                              void* d_out, int out_size)
{
    const float* x     = (const float*)d_in[0];
    const float* freqs = (const float*)d_in[1];
    const float* wq    = (const float*)d_in[2];
    const float* wk    = (const float*)d_in[3];
    const float* wv    = (const float*)d_in[4];
    const float* wo    = (const float*)d_in[5];
    const float* nqw   = (const float*)d_in[6];
    const float* nkw   = (const float*)d_in[7];
    float* out = (float*)d_out;

    float *q, *k, *v, *ao;
    cudaGetSymbolAddress((void**)&q,  g_q);
    cudaGetSymbolAddress((void**)&k,  g_k);
    cudaGetSymbolAddress((void**)&v,  g_v);
    cudaGetSymbolAddress((void**)&ao, g_ao);

    dim3 gemm_grid(D_ / 128, MROWS / 128);  // (16, 64)

    int gsm = GEMM_SMEM_FLOATS * sizeof(float);   // 147456 B
    cudaFuncSetAttribute(tgemm3_nt, cudaFuncAttributeMaxDynamicSharedMemorySize, gsm);

    tgemm3_nt<<<gemm_grid, 256, gsm>>>(x, wq, q, MROWS, D_, D_);
    tgemm3_nt<<<gemm_grid, 256, gsm>>>(x, wk, k, MROWS, D_, D_);
    tgemm3_nt<<<gemm_grid, 256, gsm>>>(x, wv, v, MROWS, D_, D_);

    rmsnorm_rope<<<dim3(MROWS * H_ / 8, 2), 256>>>(q, k, freqs, nqw, nkw);

    int fsm = FA_SMEM_FLOATS * sizeof(float);     // 163840 B
    cudaFuncSetAttribute(flash_attn_tc, cudaFuncAttributeMaxDynamicSharedMemorySize, fsm);
    flash_attn_tc<<<dim3(S_ / 128, H_, B_), 256, fsm>>>(q, k, v, ao);

    tgemm3_nt<<<gemm_grid, 256, gsm>>>(ao, wo, out, MROWS, D_, D_);
}

// round 8
// speedup vs baseline: 2.1702x; 1.2697x over previous
#include <cuda_runtime.h>
#include <cuda_bf16.h>
#include <math.h>
#include <stdint.h>

// Problem constants
#define B_  2
#define S_  4096
#define D_  2048
#define H_  16
#define HD_ 128
#define MROWS (B_ * S_)   // 8192

// Scratch in __device__ globals (allocation-guard-safe)
__device__ float g_q [(size_t)MROWS * D_];
__device__ float g_k [(size_t)MROWS * D_];
__device__ float g_v [(size_t)MROWS * D_];
__device__ float g_ao[(size_t)MROWS * D_];

// ---------------------------------------------------------------------------
// helpers
// ---------------------------------------------------------------------------
__device__ __forceinline__ float tf32r(float x) {
    uint32_t u;
    asm("cvt.rna.tf32.f32 %0, %1;" : "=r"(u) : "f"(x));
    return __uint_as_float(u);
}

__device__ __forceinline__ void mma_tf32(float* c, const uint32_t* a, const uint32_t* b) {
    asm volatile(
        "mma.sync.aligned.m16n8k8.row.col.f32.tf32.tf32.f32 "
        "{%0,%1,%2,%3}, {%4,%5,%6,%7}, {%8,%9}, {%0,%1,%2,%3};\n"
        : "+f"(c[0]), "+f"(c[1]), "+f"(c[2]), "+f"(c[3])
        : "r"(a[0]), "r"(a[1]), "r"(a[2]), "r"(a[3]), "r"(b[0]), "r"(b[1]));
}

__device__ __forceinline__ void mma_bf16(float* c, const uint32_t* a, const uint32_t* b) {
    asm volatile(
        "mma.sync.aligned.m16n8k16.row.col.f32.bf16.bf16.f32 "
        "{%0,%1,%2,%3}, {%4,%5,%6,%7}, {%8,%9}, {%0,%1,%2,%3};\n"
        : "+f"(c[0]), "+f"(c[1]), "+f"(c[2]), "+f"(c[3])
        : "r"(a[0]), "r"(a[1]), "r"(a[2]), "r"(a[3]), "r"(b[0]), "r"(b[1]));
}

// pack two floats (k-even, k-odd) into bf16x2 word (even in low half)
__device__ __forceinline__ uint32_t packbf(float a, float b) {
    __nv_bfloat162 t = __floats2bfloat162_rn(a, b);
    return *(uint32_t*)&t;
}

// ---------------------------------------------------------------------------
// 3-pass split-bf16 GEMM (error ~2^-16):
//   C[m][n] = sum_k A[m][k] * Bw[n][k]
//   C = Ahi*Bhi + Ahi*Blo + Alo*Bhi   (bf16 hi/lo split, fp32 accum)
// 128x128 tile, BK=32, 256 threads = 8 warps (2m x 4n), warp tile 64x32.
// mma.sync m16n8k16 bf16. Smem words [128][LDTW], LDTW=20 -> conflict-free.
// Double-buffered stages.
// ---------------------------------------------------------------------------
#define LDTW 20
#define GSTAGE (128 * LDTW)            // words per (array, stage)
#define GEMM_SMEM_WORDS (8 * GSTAGE)   // Ah,Al,Bh,Bl x 2 stages (81920 B)

__global__ void __launch_bounds__(256, 1) tbgemm3_nt(const float* __restrict__ A,
                                                     const float* __restrict__ Bw,
                                                     float* __restrict__ C,
                                                     int M, int N, int K)
{
    extern __shared__ uint32_t sg[];
    uint32_t* Ah = sg;                  // [2][128][LDTW]
    uint32_t* Al = Ah + 2 * GSTAGE;
    uint32_t* Bh = Al + 2 * GSTAGE;
    uint32_t* Bl = Bh + 2 * GSTAGE;

    const int tid    = threadIdx.x;
    const int warp   = tid >> 5;
    const int lane   = tid & 31;
    const int warp_m = warp >> 2;      // 0..1 -> m offset *64
    const int warp_n = warp & 3;       // 0..3 -> n offset *32
    const int g      = lane >> 2;      // group 0..7
    const int tig    = lane & 3;       // thread-in-group 0..3

    const int bm = blockIdx.y * 128;
    const int bn = blockIdx.x * 128;

    const int lrow = tid >> 3;         // 0..31
    const int lk   = (tid & 7) * 4;    // float element 0,4,...,28
    const int lkw  = (tid & 7) * 2;    // word index 0,2,...,14

    float c[4][4][4];
#pragma unroll
    for (int mi = 0; mi < 4; mi++)
#pragma unroll
        for (int ni = 0; ni < 4; ni++)
#pragma unroll
            for (int j = 0; j < 4; j++) c[mi][ni][j] = 0.0f;

    float4 av[4], bv[4];
    // prologue load k0 = 0
#pragma unroll
    for (int r = 0; r < 4; r++) {
        av[r] = *(const float4*)(A  + (size_t)(bm + lrow + 32 * r) * K + lk);
        bv[r] = *(const float4*)(Bw + (size_t)(bn + lrow + 32 * r) * K + lk);
    }

    const int iters = K / 32;
    for (int it = 0; it < iters; it++) {
        const int st = (it & 1) * GSTAGE;

        // split + store current regs into stage st
#pragma unroll
        for (int r = 0; r < 4; r++) {
            int base = st + (lrow + 32 * r) * LDTW + lkw;
            {
                float hx = __bfloat162float(__float2bfloat16(av[r].x));
                float hy = __bfloat162float(__float2bfloat16(av[r].y));
                float hz = __bfloat162float(__float2bfloat16(av[r].z));
                float hw = __bfloat162float(__float2bfloat16(av[r].w));
                Ah[base]     = packbf(hx, hy);
                Ah[base + 1] = packbf(hz, hw);
                Al[base]     = packbf(av[r].x - hx, av[r].y - hy);
                Al[base + 1] = packbf(av[r].z - hz, av[r].w - hw);
            }
            {
                float hx = __bfloat162float(__float2bfloat16(bv[r].x));
                float hy = __bfloat162float(__float2bfloat16(bv[r].y));
                float hz = __bfloat162float(__float2bfloat16(bv[r].z));
                float hw = __bfloat162float(__float2bfloat16(bv[r].w));
                Bh[base]     = packbf(hx, hy);
                Bh[base + 1] = packbf(hz, hw);
                Bl[base]     = packbf(bv[r].x - hx, bv[r].y - hy);
                Bl[base + 1] = packbf(bv[r].z - hz, bv[r].w - hw);
            }
        }
        __syncthreads();

        // prefetch next chunk
        if (it + 1 < iters) {
            const int k0 = (it + 1) * 32;
#pragma unroll
            for (int r = 0; r < 4; r++) {
                av[r] = *(const float4*)(A  + (size_t)(bm + lrow + 32 * r) * K + k0 + lk);
                bv[r] = *(const float4*)(Bw + (size_t)(bn + lrow + 32 * r) * K + k0 + lk);
            }
        }

        // compute on stage st: 2 ksteps of k16 each
#pragma unroll
        for (int kk = 0; kk < 2; kk++) {
            uint32_t ahi[4][4], alo[4][4], bhi[4][2], blo[4][2];
#pragma unroll
            for (int mi = 0; mi < 4; mi++) {
                int row = warp_m * 64 + mi * 16;
                int base0 = st + (row + g)     * LDTW + kk * 8 + tig;
                int base1 = st + (row + 8 + g) * LDTW + kk * 8 + tig;
                ahi[mi][0] = Ah[base0];
                ahi[mi][1] = Ah[base1];
                ahi[mi][2] = Ah[base0 + 4];
                ahi[mi][3] = Ah[base1 + 4];
                alo[mi][0] = Al[base0];
                alo[mi][1] = Al[base1];
                alo[mi][2] = Al[base0 + 4];
                alo[mi][3] = Al[base1 + 4];
            }
#pragma unroll
            for (int ni = 0; ni < 4; ni++) {
                int col = warp_n * 32 + ni * 8;
                int base = st + (col + g) * LDTW + kk * 8 + tig;
                bhi[ni][0] = Bh[base];
                bhi[ni][1] = Bh[base + 4];
                blo[ni][0] = Bl[base];
                blo[ni][1] = Bl[base + 4];
            }
#pragma unroll
            for (int mi = 0; mi < 4; mi++)
#pragma unroll
                for (int ni = 0; ni < 4; ni++) {
                    mma_bf16(c[mi][ni], ahi[mi], bhi[ni]);
                    mma_bf16(c[mi][ni], ahi[mi], blo[ni]);
                    mma_bf16(c[mi][ni], alo[mi], bhi[ni]);
                }
        }
        __syncthreads();
    }

#pragma unroll
    for (int mi = 0; mi < 4; mi++) {
#pragma unroll
        for (int ni = 0; ni < 4; ni++) {
            int row0 = bm + warp_m * 64 + mi * 16 + g;
            int col  = bn + warp_n * 32 + ni * 8 + 2 * tig;
            *(float2*)&C[(size_t)row0 * N + col] =
                make_float2(c[mi][ni][0], c[mi][ni][1]);
            *(float2*)&C[(size_t)(row0 + 8) * N + col] =
                make_float2(c[mi][ni][2], c[mi][ni][3]);
        }
    }
}

// ---------------------------------------------------------------------------
// Per-head RMSNorm + RoPE, in place on q and k.
// ---------------------------------------------------------------------------
__global__ void __launch_bounds__(256) rmsnorm_rope(float* __restrict__ qp,
                                                    float* __restrict__ kp,
                                                    const float* __restrict__ freqs,
                                                    const float* __restrict__ wq,
                                                    const float* __restrict__ wk)
{
    float* ptr      = blockIdx.y ? kp : qp;
    const float* w  = blockIdx.y ? wk : wq;

    const int warp = threadIdx.x >> 5;
    const int lane = threadIdx.x & 31;
    const size_t row = (size_t)blockIdx.x * 8 + warp;   // 0 .. B*S*H-1
    const size_t bs  = row >> 4;                        // (b*S + s)

    float4 xv = *(float4*)&ptr[row * HD_ + lane * 4];
    float ss = xv.x * xv.x + xv.y * xv.y + xv.z * xv.z + xv.w * xv.w;
#pragma unroll
    for (int off = 16; off; off >>= 1) ss += __shfl_xor_sync(0xffffffffu, ss, off);
    float r = rsqrtf(ss * (1.0f / 128.0f) + 1e-5f);

    float4 wv = *(const float4*)&w[lane * 4];
    float nr0 = xv.x * r * wv.x;
    float ni0 = xv.y * r * wv.y;
    float nr1 = xv.z * r * wv.z;
    float ni1 = xv.w * r * wv.w;

    const float* f = freqs + bs * HD_;
    float c0 = f[2 * lane],     c1 = f[2 * lane + 1];
    float s0 = f[64 + 2 * lane], s1 = f[64 + 2 * lane + 1];

    float4 o;
    o.x = nr0 * c0 - ni0 * s0;
    o.y = nr0 * s0 + ni0 * c0;
    o.z = nr1 * c1 - ni1 * s1;
    o.w = nr1 * s1 + ni1 * c1;
    *(float4*)&ptr[row * HD_ + lane * 4] = o;
}

// ---------------------------------------------------------------------------
// Tensor-core flash attention (tf32 mma, fp32 softmax/accum). UNCHANGED.
// Br=128 q rows per CTA, Bc=64 kv per tile, 8 warps x 16 rows.
// Fragment-major smem layouts (conflict-free wide LDS).
// ---------------------------------------------------------------------------
#define FQF (8 * 16 * 128)   // 16384 floats
#define FKF (16 * 8 * 64)    // 8192
#define FVF (8 * 16 * 64)    // 8192
#define FPF (8 * 8 * 128)    // 8192
#define FA_SMEM_FLOATS (FQF + FKF + FVF + FPF)   // 40960 floats = 160KB

__global__ void __launch_bounds__(256, 1) flash_attn_tc(const float* __restrict__ q,
                                                        const float* __restrict__ k,
                                                        const float* __restrict__ v,
                                                        float* __restrict__ out)
{
    extern __shared__ float sm[];
    float* Qf = sm;
    float* Kf = Qf + FQF;
    float* Vf = Kf + FKF;
    float* Pf = Vf + FVF;

    const int b   = blockIdx.z;
    const int h   = blockIdx.y;
    const int q0  = blockIdx.x * 128;
    const int tid = threadIdx.x;
    const int w   = tid >> 5;
    const int lane = tid & 31;
    const int g   = lane >> 2;
    const int tig = lane & 3;

    const float scale = 0.08838834764831845f;  // 1/sqrt(128)

    // ---- Load Q tile into fragment-major smem, pre-scaled, tf32-rounded ----
    for (int i = tid; i < 128 * 32; i += 256) {
        int r  = i >> 5;
        int c0 = (i & 31) * 4;
        float4 val = *(const float4*)&q[(size_t)(b * S_ + q0 + r) * D_ + h * HD_ + c0];
        int wd = r >> 4, gg = r & 15;
        int rowhi = gg >> 3, gd = gg & 7;
        int kk = c0 >> 3, hi = (c0 >> 2) & 1;
        int jb = hi * 2 + rowhi;
        float vals[4] = {val.x, val.y, val.z, val.w};
#pragma unroll
        for (int j4 = 0; j4 < 4; j4++) {
            int laned = 4 * gd + j4;
            Qf[((wd * 16 + kk) * 32 + laned) * 4 + jb] = tf32r(vals[j4] * scale);
        }
    }

    float m[2], l[2], o[16][4];
    m[0] = m[1] = -INFINITY;
    l[0] = l[1] = 0.0f;
#pragma unroll
    for (int nt = 0; nt < 16; nt++)
#pragma unroll
        for (int j = 0; j < 4; j++) o[nt][j] = 0.0f;

    for (int kv0 = 0; kv0 < S_; kv0 += 64) {
        __syncthreads();   // Kf/Vf free (prev tile done); also covers Qf on iter 0

        // ---- Load K,V tiles into fragment-major smem ----
        for (int i = tid; i < 64 * 32; i += 256) {
            int r  = i >> 5;
            int c0 = (i & 31) * 4;
            size_t gbase = (size_t)(b * S_ + kv0 + r) * D_ + h * HD_ + c0;
            // K: n = kv row (r), k = dim (c)
            {
                float4 val = *(const float4*)&k[gbase];
                int nt = r >> 3, gd = r & 7;
                int kk = c0 >> 3, slot = (c0 >> 2) & 1;
                float vals[4] = {val.x, val.y, val.z, val.w};
#pragma unroll
                for (int j4 = 0; j4 < 4; j4++) {
                    int laned = 4 * gd + j4;
                    Kf[((kk * 8 + nt) * 32 + laned) * 2 + slot] = tf32r(vals[j4]);
                }
            }
            // V: k = kv row (r), n = dim (c)
            {
                float4 val = *(const float4*)&v[gbase];
                int kk = r >> 3, tv = r & 7;
                int slot = tv >> 2, tg = tv & 3;
                int nt = c0 >> 3;
                int g0 = c0 & 7;
                float vals[4] = {val.x, val.y, val.z, val.w};
#pragma unroll
                for (int j4 = 0; j4 < 4; j4++) {
                    int laned = 4 * (g0 + j4) + tg;
                    Vf[((kk * 16 + nt) * 32 + laned) * 2 + slot] = tf32r(vals[j4]);
                }
            }
        }
        __syncthreads();

        // ---- S = Q K^T (scaled already) ----
        float sc[8][4];
#pragma unroll
        for (int nt = 0; nt < 8; nt++)
#pragma unroll
            for (int j = 0; j < 4; j++) sc[nt][j] = 0.0f;

#pragma unroll
        for (int kk = 0; kk < 16; kk++) {
            float4 a4 = *(const float4*)&Qf[((w * 16 + kk) * 32 + lane) * 4];
            uint32_t a[4] = {__float_as_uint(a4.x), __float_as_uint(a4.y),
                             __float_as_uint(a4.z), __float_as_uint(a4.w)};
#pragma unroll
            for (int nt = 0; nt < 8; nt++) {
                float2 b2 = *(const float2*)&Kf[((kk * 8 + nt) * 32 + lane) * 2];
                uint32_t bb[2] = {__float_as_uint(b2.x), __float_as_uint(b2.y)};
                mma_tf32(sc[nt], a, bb);
            }
        }

        // ---- online softmax (rows g and g+8 of this warp's 16-row block) ----
#pragma unroll
        for (int rh = 0; rh < 2; rh++) {
            int i0 = rh * 2;
            float rm = -INFINITY;
#pragma unroll
            for (int nt = 0; nt < 8; nt++)
                rm = fmaxf(rm, fmaxf(sc[nt][i0], sc[nt][i0 + 1]));
            rm = fmaxf(rm, __shfl_xor_sync(0xffffffffu, rm, 1));
            rm = fmaxf(rm, __shfl_xor_sync(0xffffffffu, rm, 2));
            float mnew = fmaxf(m[rh], rm);
            float alpha = __expf(m[rh] - mnew);
            float rs = 0.0f;
#pragma unroll
            for (int nt = 0; nt < 8; nt++) {
                sc[nt][i0]     = __expf(sc[nt][i0]     - mnew);
                sc[nt][i0 + 1] = __expf(sc[nt][i0 + 1] - mnew);
                rs += sc[nt][i0] + sc[nt][i0 + 1];
            }
            rs += __shfl_xor_sync(0xffffffffu, rs, 1);
            rs += __shfl_xor_sync(0xffffffffu, rs, 2);
            l[rh] = l[rh] * alpha + rs;
            m[rh] = mnew;
#pragma unroll
            for (int nt = 0; nt < 16; nt++) {
                o[nt][i0]     *= alpha;
                o[nt][i0 + 1] *= alpha;
            }
        }

        // ---- store P fragments (per-warp private region) ----
#pragma unroll
        for (int nt = 0; nt < 8; nt++) {
#pragma unroll
            for (int e = 0; e < 2; e++) {
                int t  = 2 * tig + e;
                int hi = t >> 2, tg = t & 3;
                int laned = 4 * g + tg;
#pragma unroll
                for (int rh = 0; rh < 2; rh++) {
                    int jb = hi * 2 + rh;
                    Pf[((w * 8 + nt) * 32 + laned) * 4 + jb] = tf32r(sc[nt][rh * 2 + e]);
                }
            }
        }
        __syncwarp();

        // ---- O += P V ----
#pragma unroll
        for (int kk = 0; kk < 8; kk++) {
            float4 a4 = *(const float4*)&Pf[((w * 8 + kk) * 32 + lane) * 4];
            uint32_t a[4] = {__float_as_uint(a4.x), __float_as_uint(a4.y),
                             __float_as_uint(a4.z), __float_as_uint(a4.w)};
#pragma unroll
            for (int nt = 0; nt < 16; nt++) {
                float2 b2 = *(const float2*)&Vf[((kk * 16 + nt) * 32 + lane) * 2];
                uint32_t bb[2] = {__float_as_uint(b2.x), __float_as_uint(b2.y)};
                mma_tf32(o[nt], a, bb);
            }
        }
    }

    // ---- normalize + write out ----
    float inv0 = 1.0f / l[0];
    float inv1 = 1.0f / l[1];
    size_t row0 = (size_t)(b * S_ + q0 + w * 16 + g);
    size_t row1 = row0 + 8;
#pragma unroll
    for (int nt = 0; nt < 16; nt++) {
        int col = h * HD_ + nt * 8 + 2 * tig;
        *(float2*)&out[row0 * D_ + col] = make_float2(o[nt][0] * inv0, o[nt][1] * inv0);
        *(float2*)&out[row1 * D_ + col] = make_float2(o[nt][2] * inv1, o[nt][3] * inv1);
    }
}

// ---------------------------------------------------------------------------
// Launch
// ---------------------------------------------------------------------------
extern "C" void kernel_launch(void* const* d_in, const int* in_sizes, int n_in,
                              void* d_out, int out_size)
{
    const float* x     = (const float*)d_in[0];
    const float* freqs = (const float*)d_in[1];
    const float* wq    = (const float*)d_in[2];
    const float* wk    = (const float*)d_in[3];
    const float* wv    = (const float*)d_in[4];
    const float* wo    = (const float*)d_in[5];
    const float* nqw   = (const float*)d_in[6];
    const float* nkw   = (const float*)d_in[7];
    float* out = (float*)d_out;

    float *q, *k, *v, *ao;
    cudaGetSymbolAddress((void**)&q,  g_q);
    cudaGetSymbolAddress((void**)&k,  g_k);
    cudaGetSymbolAddress((void**)&v,  g_v);
    cudaGetSymbolAddress((void**)&ao, g_ao);

    dim3 gemm_grid(D_ / 128, MROWS / 128);  // (16, 64)

    int gsm = GEMM_SMEM_WORDS * sizeof(uint32_t);   // 81920 B
    cudaFuncSetAttribute(tbgemm3_nt, cudaFuncAttributeMaxDynamicSharedMemorySize, gsm);

    tbgemm3_nt<<<gemm_grid, 256, gsm>>>(x, wq, q, MROWS, D_, D_);
    tbgemm3_nt<<<gemm_grid, 256, gsm>>>(x, wk, k, MROWS, D_, D_);
    tbgemm3_nt<<<gemm_grid, 256, gsm>>>(x, wv, v, MROWS, D_, D_);

    rmsnorm_rope<<<dim3(MROWS * H_ / 8, 2), 256>>>(q, k, freqs, nqw, nkw);

    int fsm = FA_SMEM_FLOATS * sizeof(float);     // 163840 B
    cudaFuncSetAttribute(flash_attn_tc, cudaFuncAttributeMaxDynamicSharedMemorySize, fsm);
    flash_attn_tc<<<dim3(S_ / 128, H_, B_), 256, fsm>>>(q, k, v, ao);

    tbgemm3_nt<<<gemm_grid, 256, gsm>>>(ao, wo, out, MROWS, D_, D_);
}